// round 2
// baseline (speedup 1.0000x reference)
#include <cuda_runtime.h>
#include <cstdint>
#include <math.h>

// ---------------------------------------------------------------------------
// Problem constants
//   b=4, tokens S=1024 (=c), features D=8192 (=n*h*w), heads=8, d_k=d_v=256
// ---------------------------------------------------------------------------
#define BATCH      4
#define SEQ        1024
#define DEMB       8192
#define NHEAD      8
#define DKV        256
#define QKVDIM     (NHEAD * DKV)          // 2048
#define TOK_TOTAL  (BATCH * SEQ)          // 4096
#define PLANE      ((long)SEQ * DEMB)     // 8,388,608 per batch

// ---------------------------------------------------------------------------
// Scratch (static device allocations — no cudaMalloc allowed)
// ---------------------------------------------------------------------------
__device__ float  g_X[(long)BATCH * SEQ * DEMB];     // 134 MB
__device__ float  g_Q[(long)BATCH * SEQ * QKVDIM];   // 33.5 MB
__device__ float  g_K[(long)BATCH * SEQ * QKVDIM];
__device__ float  g_V[(long)BATCH * SEQ * QKVDIM];
__device__ float  g_S[(long)BATCH * NHEAD * SEQ * SEQ]; // 134 MB
__device__ float  g_Z[(long)BATCH * SEQ * QKVDIM];
__device__ float  g_O[(long)BATCH * SEQ * DEMB];     // 134 MB
__device__ double g_part[BATCH * 1024 * 2];
__device__ double g_mean[BATCH];
__device__ double g_rstd[BATCH];

// ---------------------------------------------------------------------------
// Kernel 1: build X[b, t, f] = concat/transpose(ref,hd) + 0.001 * PE(t, f)
// Input layout ref/hd: [b, n, h, w16, c=1024]; f = n*1024 + h*32 + w,
// token t = c index. This is a [f][t] -> [t][f] transpose per batch: use
// 32x32 smem tiles so both sides are coalesced.
// PE: both sin (even f) and cos (odd f) use freq = 10000^(-f/4096).
// ---------------------------------------------------------------------------
__global__ void build_x_kernel(const float* __restrict__ ref,
                               const float* __restrict__ hd,
                               float* __restrict__ X)
{
    __shared__ float tile[32][33];
    const int b  = blockIdx.z;
    const int f0 = blockIdx.x * 32;
    const int t0 = blockIdx.y * 32;
    const int tx = threadIdx.x, ty = threadIdx.y;

#pragma unroll
    for (int i = 0; i < 4; i++) {
        int f  = f0 + ty + i * 8;
        int n_ = f >> 10;
        int s  = f & 1023;
        int hh = s >> 5;
        int ww = s & 31;
        const float* src = (ww < 16)
            ? ref + ((long)(((b * 8 + n_) * 32 + hh) * 16 + ww)) * 1024
            : hd  + ((long)(((b * 8 + n_) * 32 + hh) * 16 + (ww - 16))) * 1024;
        tile[ty + i * 8][tx] = src[t0 + tx];
    }
    __syncthreads();
#pragma unroll
    for (int i = 0; i < 4; i++) {
        int t = t0 + ty + i * 8;
        int f = f0 + tx;
        float freq = __expf((float)f * (-9.210340371976184f / 4096.0f)); // 10000^(-f/4096)
        float ang  = (float)t * freq;
        float pe   = (f & 1) ? cosf(ang) : sinf(ang);
        X[(long)b * PLANE + (long)t * DEMB + f] = tile[tx][ty + i * 8] + 0.001f * pe;
    }
}

// ---------------------------------------------------------------------------
// Batched strided SGEMM: C = alpha * A * op(B) (+ D)
//   TB=false: B is [K,N] row-major;  TB=true: B is [N,K] row-major (B^T)
// Block tile 128x128x8, 256 threads, 8x8 register tile per thread.
// Batch offset for each of A/B/C: (z/inner)*so + (z%inner)*si.
// All M,N multiples of 128, K multiple of 8 -> no bounds checks.
// ---------------------------------------------------------------------------
template <bool TB>
__global__ __launch_bounds__(256)
void gemm_kernel(const float* __restrict__ A, int lda, long sAo, long sAi,
                 const float* __restrict__ B, int ldb, long sBo, long sBi,
                 float* __restrict__ C, int ldc, long sCo, long sCi,
                 const float* __restrict__ D,
                 int K, int inner, float alpha)
{
    const int z  = blockIdx.z;
    const int zo = z / inner, zi = z % inner;
    A += zo * sAo + zi * sAi;
    B += zo * sBo + zi * sBi;
    C += zo * sCo + zi * sCi;
    if (D) D += zo * sCo + zi * sCi;

    __shared__ float As[8][132];   // padded: conflict-free transposed stores
    __shared__ float Bs[8][128];

    const int tid  = threadIdx.x;
    const int tx   = tid & 15;          // 16 col-threads
    const int ty   = tid >> 4;          // 16 row-threads
    const int row0 = blockIdx.y * 128;
    const int col0 = blockIdx.x * 128;

    const int a_row = tid >> 1;           // 0..127
    const int a_k   = (tid & 1) * 4;      // 0 or 4
    const int b_k   = tid >> 5;           // 0..7   (NN path)
    const int b_col = (tid & 31) * 4;     // 0..124 (NN path)

    float acc[8][8];
#pragma unroll
    for (int i = 0; i < 8; i++)
#pragma unroll
        for (int j = 0; j < 8; j++) acc[i][j] = 0.f;

    for (int k0 = 0; k0 < K; k0 += 8) {
        // --- load A tile [128][8], store transposed As[k][m]
        float4 av = *(const float4*)(A + (long)(row0 + a_row) * lda + k0 + a_k);
        As[a_k + 0][a_row] = av.x;
        As[a_k + 1][a_row] = av.y;
        As[a_k + 2][a_row] = av.z;
        As[a_k + 3][a_row] = av.w;
        // --- load B tile
        if (TB) {
            // B is [N,K]: Bs[k][n] = B[col0+n][k0+k]
            float4 bv = *(const float4*)(B + (long)(col0 + a_row) * ldb + k0 + a_k);
            Bs[a_k + 0][a_row] = bv.x;
            Bs[a_k + 1][a_row] = bv.y;
            Bs[a_k + 2][a_row] = bv.z;
            Bs[a_k + 3][a_row] = bv.w;
        } else {
            float4 bv = *(const float4*)(B + (long)(k0 + b_k) * ldb + col0 + b_col);
            *(float4*)&Bs[b_k][b_col] = bv;
        }
        __syncthreads();

#pragma unroll
        for (int k = 0; k < 8; k++) {
            float a[8], bb[8];
            float4 a0 = *(const float4*)&As[k][ty * 8];
            float4 a1 = *(const float4*)&As[k][ty * 8 + 4];
            a[0]=a0.x; a[1]=a0.y; a[2]=a0.z; a[3]=a0.w;
            a[4]=a1.x; a[5]=a1.y; a[6]=a1.z; a[7]=a1.w;
            float4 b0 = *(const float4*)&Bs[k][tx * 8];
            float4 b1 = *(const float4*)&Bs[k][tx * 8 + 4];
            bb[0]=b0.x; bb[1]=b0.y; bb[2]=b0.z; bb[3]=b0.w;
            bb[4]=b1.x; bb[5]=b1.y; bb[6]=b1.z; bb[7]=b1.w;
#pragma unroll
            for (int i = 0; i < 8; i++)
#pragma unroll
                for (int j = 0; j < 8; j++)
                    acc[i][j] = fmaf(a[i], bb[j], acc[i][j]);
        }
        __syncthreads();
    }

    // --- epilogue (vectorized, optional residual add)
#pragma unroll
    for (int i = 0; i < 8; i++) {
        long off = (long)(row0 + ty * 8 + i) * ldc + col0 + tx * 8;
        float4 v0 = make_float4(acc[i][0]*alpha, acc[i][1]*alpha, acc[i][2]*alpha, acc[i][3]*alpha);
        float4 v1 = make_float4(acc[i][4]*alpha, acc[i][5]*alpha, acc[i][6]*alpha, acc[i][7]*alpha);
        if (D) {
            float4 d0 = *(const float4*)(D + off);
            float4 d1 = *(const float4*)(D + off + 4);
            v0.x += d0.x; v0.y += d0.y; v0.z += d0.z; v0.w += d0.w;
            v1.x += d1.x; v1.y += d1.y; v1.z += d1.z; v1.w += d1.w;
        }
        *(float4*)(C + off)     = v0;
        *(float4*)(C + off + 4) = v1;
    }
}

// ---------------------------------------------------------------------------
// Softmax over rows of S (row length 1024). One 256-thread block per row.
// ---------------------------------------------------------------------------
__global__ void softmax_kernel(float* __restrict__ S)
{
    __shared__ float red[8];
    const int tid  = threadIdx.x;
    const int lane = tid & 31, warp = tid >> 5;
    float4* row = (float4*)(S + (long)blockIdx.x * SEQ);
    float4 v = row[tid];

    float m = fmaxf(fmaxf(v.x, v.y), fmaxf(v.z, v.w));
#pragma unroll
    for (int o = 16; o; o >>= 1) m = fmaxf(m, __shfl_xor_sync(~0u, m, o));
    if (lane == 0) red[warp] = m;
    __syncthreads();
    float M = red[0];
#pragma unroll
    for (int i = 1; i < 8; i++) M = fmaxf(M, red[i]);

    v.x = __expf(v.x - M); v.y = __expf(v.y - M);
    v.z = __expf(v.z - M); v.w = __expf(v.w - M);
    float s = v.x + v.y + v.z + v.w;
#pragma unroll
    for (int o = 16; o; o >>= 1) s += __shfl_xor_sync(~0u, s, o);
    __syncthreads();                    // protect red[] reuse
    if (lane == 0) red[warp] = s;
    __syncthreads();
    float T = 0.f;
#pragma unroll
    for (int i = 0; i < 8; i++) T += red[i];
    float inv = 1.0f / T;
    v.x *= inv; v.y *= inv; v.z *= inv; v.w *= inv;
    row[tid] = v;
}

// ---------------------------------------------------------------------------
// Deterministic two-stage mean/var over each batch's [1024, 8192] slab.
// ---------------------------------------------------------------------------
__global__ void reduce_partial_kernel(const float* __restrict__ O,
                                      double* __restrict__ part)
{
    __shared__ double sh[256], sh2[256];
    const int b   = blockIdx.y;
    const int tid = threadIdx.x;
    const float* p = O + (long)b * PLANE;
    const int base = blockIdx.x * 256 + tid;      // 0..262143
    double s = 0.0, s2 = 0.0;
#pragma unroll
    for (int i = 0; i < 32; i++) {
        float v = p[base + i * 262144];
        s  += v;
        s2 += (double)v * v;
    }
    sh[tid] = s; sh2[tid] = s2;
    __syncthreads();
    for (int o = 128; o; o >>= 1) {
        if (tid < o) { sh[tid] += sh[tid + o]; sh2[tid] += sh2[tid + o]; }
        __syncthreads();
    }
    if (tid == 0) {
        part[(b * 1024 + blockIdx.x) * 2 + 0] = sh[0];
        part[(b * 1024 + blockIdx.x) * 2 + 1] = sh2[0];
    }
}

__global__ void finalize_stats_kernel(const double* __restrict__ part)
{
    __shared__ double sh[256], sh2[256];
    const int b = blockIdx.x, tid = threadIdx.x;
    double s = 0.0, s2 = 0.0;
    for (int i = tid; i < 1024; i += 256) {
        s  += part[(b * 1024 + i) * 2 + 0];
        s2 += part[(b * 1024 + i) * 2 + 1];
    }
    sh[tid] = s; sh2[tid] = s2;
    __syncthreads();
    for (int o = 128; o; o >>= 1) {
        if (tid < o) { sh[tid] += sh[tid + o]; sh2[tid] += sh2[tid + o]; }
        __syncthreads();
    }
    if (tid == 0) {
        double n    = (double)PLANE;
        double mean = sh[0] / n;
        double var  = sh2[0] / n - mean * mean;
        g_mean[b] = mean;
        g_rstd[b] = rsqrt(var + 1e-6);
    }
}

// ---------------------------------------------------------------------------
// LayerNorm + output transpose:
//   out[b, n_, c_, h_, w_] = LN(O)[b, t=h_*32+w_, f=n_*1024+c_]
// i.e. per (b, n_): a 1024x1024 transpose of the feature sub-plane.
// ---------------------------------------------------------------------------
__global__ void ln_out_kernel(const float* __restrict__ O,
                              const float* __restrict__ gamma,
                              const float* __restrict__ beta,
                              float* __restrict__ out)
{
    __shared__ float tile[32][33];
    const int bz = blockIdx.z;          // b*8 + n_
    const int b  = bz >> 3;
    const int nf = (bz & 7) * 1024;     // feature offset of this head-plane
    const int c0 = blockIdx.x * 32;
    const int t0 = blockIdx.y * 32;
    const int tx = threadIdx.x, ty = threadIdx.y;
    const float mean = (float)g_mean[b];
    const float rstd = (float)g_rstd[b];

#pragma unroll
    for (int i = 0; i < 4; i++) {
        int t   = t0 + ty + i * 8;
        long fi = (long)t * DEMB + nf + c0 + tx;
        float v = O[(long)b * PLANE + fi];
        tile[ty + i * 8][tx] = (v - mean) * rstd * gamma[fi] + beta[fi];
    }
    __syncthreads();
#pragma unroll
    for (int i = 0; i < 4; i++) {
        int c = c0 + ty + i * 8;
        out[((long)bz * 1024 + c) * 1024 + t0 + tx] = tile[tx][ty + i * 8];
    }
}

// ---------------------------------------------------------------------------
// Launcher
// ---------------------------------------------------------------------------
extern "C" void kernel_launch(void* const* d_in, const int* in_sizes, int n_in,
                              void* d_out, int out_size)
{
    const float* ref_img = (const float*)d_in[0];
    const float* hdmap   = (const float*)d_in[1];
    const float* w_q     = (const float*)d_in[2];
    const float* w_k     = (const float*)d_in[3];
    const float* w_v     = (const float*)d_in[4];
    const float* w_o     = (const float*)d_in[5];
    const float* gamma   = (const float*)d_in[6];
    const float* beta    = (const float*)d_in[7];
    float* out = (float*)d_out;

    float *X, *Q, *Kb, *V, *S, *Z, *O;
    double* part;
    cudaGetSymbolAddress((void**)&X,    g_X);
    cudaGetSymbolAddress((void**)&Q,    g_Q);
    cudaGetSymbolAddress((void**)&Kb,   g_K);
    cudaGetSymbolAddress((void**)&V,    g_V);
    cudaGetSymbolAddress((void**)&S,    g_S);
    cudaGetSymbolAddress((void**)&Z,    g_Z);
    cudaGetSymbolAddress((void**)&O,    g_O);
    cudaGetSymbolAddress((void**)&part, g_part);

    const dim3 tb32x8(32, 8);

    // 1) build X (gather + transpose + PE)
    build_x_kernel<<<dim3(DEMB / 32, SEQ / 32, BATCH), tb32x8>>>(ref_img, hdmap, X);

    // 2) Q/K/V projections: [4096,8192] x [8192,2048]
    const dim3 gp(QKVDIM / 128, TOK_TOTAL / 128, 1);
    gemm_kernel<false><<<gp, 256>>>(X, DEMB, 0, 0, w_q, QKVDIM, 0, 0,
                                    Q, QKVDIM, 0, 0, nullptr, DEMB, 1, 1.0f);
    gemm_kernel<false><<<gp, 256>>>(X, DEMB, 0, 0, w_k, QKVDIM, 0, 0,
                                    Kb, QKVDIM, 0, 0, nullptr, DEMB, 1, 1.0f);
    gemm_kernel<false><<<gp, 256>>>(X, DEMB, 0, 0, w_v, QKVDIM, 0, 0,
                                    V, QKVDIM, 0, 0, nullptr, DEMB, 1, 1.0f);

    // 3) scores: per (b,h): S = (1/16) * Q_h K_h^T  [1024x1024x256], 32 batches
    const long sQKb = (long)SEQ * QKVDIM;       // per-batch stride in Q/K/V
    const long sSb  = (long)NHEAD * SEQ * SEQ;  // per-batch stride in S
    gemm_kernel<true><<<dim3(SEQ / 128, SEQ / 128, BATCH * NHEAD), 256>>>(
        Q,  QKVDIM, sQKb, DKV,
        Kb, QKVDIM, sQKb, DKV,
        S,  SEQ,    sSb,  (long)SEQ * SEQ,
        nullptr, DKV, NHEAD, 0.0625f);

    // 4) softmax rows
    softmax_kernel<<<BATCH * NHEAD * SEQ, 256>>>(S);

    // 5) Z = P @ V_h  [1024x256x1024], 32 batches
    gemm_kernel<false><<<dim3(DKV / 128, SEQ / 128, BATCH * NHEAD), 256>>>(
        S, SEQ,    sSb,  (long)SEQ * SEQ,
        V, QKVDIM, sQKb, DKV,
        Z, QKVDIM, sQKb, DKV,
        nullptr, SEQ, NHEAD, 1.0f);

    // 6) O = Z @ w_o + X (residual)  [4096,2048]x[2048,8192]
    gemm_kernel<false><<<dim3(DEMB / 128, TOK_TOTAL / 128, 1), 256>>>(
        Z, QKVDIM, 0, 0, w_o, DEMB, 0, 0,
        O, DEMB, 0, 0, X, QKVDIM, 1, 1.0f);

    // 7) LayerNorm statistics (deterministic two-stage, fp64 accumulation)
    reduce_partial_kernel<<<dim3(1024, BATCH), 256>>>(O, part);
    finalize_stats_kernel<<<BATCH, 256>>>(part);

    // 8) normalize + final transpose to [b, n, c, h, w]
    ln_out_kernel<<<dim3(32, 32, BATCH * NHEAD), tb32x8>>>(O, gamma, beta, out);
}

// round 5
// speedup vs baseline: 3.0033x; 3.0033x over previous
#include <cuda_runtime.h>
#include <cuda_bf16.h>
#include <cstdint>
#include <math.h>

// ---------------------------------------------------------------------------
// Problem constants
// ---------------------------------------------------------------------------
#define BATCH      4
#define SEQ        1024
#define DEMB       8192
#define NHEAD      8
#define DKV        256
#define QKVDIM     (NHEAD * DKV)          // 2048
#define TOK_TOTAL  (BATCH * SEQ)          // 4096
#define PLANE      ((long)SEQ * DEMB)

// ---------------------------------------------------------------------------
// Scratch (static device allocations — no cudaMalloc allowed)
// ---------------------------------------------------------------------------
__device__ __align__(256) float  g_X[(long)BATCH * SEQ * DEMB];
__device__ __align__(256) float  g_Q[(long)BATCH * SEQ * QKVDIM];
__device__ __align__(256) float  g_K[(long)BATCH * SEQ * QKVDIM];
__device__ __align__(256) float  g_V[(long)BATCH * SEQ * QKVDIM];
__device__ __align__(256) float  g_S[(long)BATCH * NHEAD * SEQ * SEQ];
__device__ __align__(256) float  g_Z[(long)BATCH * SEQ * QKVDIM];
__device__ __align__(256) float  g_O[(long)BATCH * SEQ * DEMB];
__device__ double g_part[BATCH * 1024 * 2];
__device__ double g_mean[BATCH];
__device__ double g_rstd[BATCH];

// bf16 hi/lo split operands
__device__ __align__(256) __nv_bfloat16 g_Xh[(long)BATCH * SEQ * DEMB];
__device__ __align__(256) __nv_bfloat16 g_Xl[(long)BATCH * SEQ * DEMB];
__device__ __align__(256) __nv_bfloat16 g_Wqth[(long)QKVDIM * DEMB];
__device__ __align__(256) __nv_bfloat16 g_Wqtl[(long)QKVDIM * DEMB];
__device__ __align__(256) __nv_bfloat16 g_Wkth[(long)QKVDIM * DEMB];
__device__ __align__(256) __nv_bfloat16 g_Wktl[(long)QKVDIM * DEMB];
__device__ __align__(256) __nv_bfloat16 g_Wvth[(long)QKVDIM * DEMB];
__device__ __align__(256) __nv_bfloat16 g_Wvtl[(long)QKVDIM * DEMB];
__device__ __align__(256) __nv_bfloat16 g_Woth[(long)DEMB * QKVDIM];
__device__ __align__(256) __nv_bfloat16 g_Wotl[(long)DEMB * QKVDIM];
__device__ __align__(256) __nv_bfloat16 g_Qh[(long)BATCH * SEQ * QKVDIM];
__device__ __align__(256) __nv_bfloat16 g_Ql[(long)BATCH * SEQ * QKVDIM];
__device__ __align__(256) __nv_bfloat16 g_Kh[(long)BATCH * SEQ * QKVDIM];
__device__ __align__(256) __nv_bfloat16 g_Kl[(long)BATCH * SEQ * QKVDIM];
__device__ __align__(256) __nv_bfloat16 g_Vth[(long)BATCH * NHEAD * DKV * SEQ];
__device__ __align__(256) __nv_bfloat16 g_Vtl[(long)BATCH * NHEAD * DKV * SEQ];
__device__ __align__(256) __nv_bfloat16 g_Ph[(long)BATCH * NHEAD * SEQ * SEQ];
__device__ __align__(256) __nv_bfloat16 g_Pl[(long)BATCH * NHEAD * SEQ * SEQ];
__device__ __align__(256) __nv_bfloat16 g_Zh[(long)BATCH * SEQ * QKVDIM];
__device__ __align__(256) __nv_bfloat16 g_Zl[(long)BATCH * SEQ * QKVDIM];

// ---------------------------------------------------------------------------
// PTX helpers (all sm_80-compatible: cp.async, ldmatrix, mma.sync)
// ---------------------------------------------------------------------------
__device__ __forceinline__ uint32_t smem_u32(const void* p) {
    uint32_t a;
    asm("{ .reg .u64 t; cvta.to.shared.u64 t, %1; cvt.u32.u64 %0, t; }"
        : "=r"(a) : "l"(p));
    return a;
}
__device__ __forceinline__ void cpasync16(uint32_t dst, const void* src) {
    asm volatile("cp.async.cg.shared.global [%0], [%1], 16;" :: "r"(dst), "l"(src));
}
__device__ __forceinline__ void cp_commit() {
    asm volatile("cp.async.commit_group;" ::: "memory");
}
template <int N> __device__ __forceinline__ void cp_wait() {
    asm volatile("cp.async.wait_group %0;" :: "n"(N) : "memory");
}
__device__ __forceinline__ void ldsm4(uint32_t* r, uint32_t addr) {
    asm volatile("ldmatrix.sync.aligned.m8n8.x4.shared.b16 {%0,%1,%2,%3}, [%4];"
                 : "=r"(r[0]), "=r"(r[1]), "=r"(r[2]), "=r"(r[3]) : "r"(addr));
}
__device__ __forceinline__ void ldsm2(uint32_t* r, uint32_t addr) {
    asm volatile("ldmatrix.sync.aligned.m8n8.x2.shared.b16 {%0,%1}, [%2];"
                 : "=r"(r[0]), "=r"(r[1]) : "r"(addr));
}
__device__ __forceinline__ void mma16816(float* c, const uint32_t* a, const uint32_t* b) {
    asm volatile(
        "mma.sync.aligned.m16n8k16.row.col.f32.bf16.bf16.f32 "
        "{%0,%1,%2,%3}, {%4,%5,%6,%7}, {%8,%9}, {%0,%1,%2,%3};"
        : "+f"(c[0]), "+f"(c[1]), "+f"(c[2]), "+f"(c[3])
        : "r"(a[0]), "r"(a[1]), "r"(a[2]), "r"(a[3]), "r"(b[0]), "r"(b[1]));
}

// ---------------------------------------------------------------------------
// Split-precision bf16 GEMM on mma.sync (HMMA).
// C[M,N] = alpha * (Ah*Bh^T + Ah*Bl^T + Al*Bh^T) (+ D), fp32 accum in regs.
// A*: [M,K] bf16 row-major (lda). B*: [N,K] bf16 row-major (ldb).
// Block 128x128, K-chunk 64, 3-stage cp.async pipeline, XOR-swizzled smem.
// Batch z: offset = (z/inner)*so + (z%inner)*si per operand.
// ---------------------------------------------------------------------------
#define KC      64
#define TILE_B  16384                     // 128 rows x 128 bytes
#define STG_B   (4 * TILE_B)              // Ah, Al, Bh, Bl per stage
#define NSTAGE  3
#define SMEM_DYN (NSTAGE * STG_B)         // 196608

__global__ __launch_bounds__(256, 1)
void mma_gemm(const __nv_bfloat16* __restrict__ Ah, const __nv_bfloat16* __restrict__ Al,
              int lda, long sAo, long sAi,
              const __nv_bfloat16* __restrict__ Bh, const __nv_bfloat16* __restrict__ Bl,
              int ldb, long sBo, long sBi,
              float* __restrict__ C, int ldc, long sCo, long sCi,
              const float* __restrict__ D,
              int K, int inner, float alpha)
{
    extern __shared__ char dsm_raw[];
    const uint32_t dsm0 = smem_u32(dsm_raw);

    const int tid  = threadIdx.x;
    const int lane = tid & 31;
    const int wid  = tid >> 5;
    const int wm   = wid & 1;             // warp row (2)
    const int wn   = wid >> 1;            // warp col (4)

    const int z  = blockIdx.z;
    const int zo = z / inner, zi = z - zo * inner;
    Ah += zo * sAo + zi * sAi;  Al += zo * sAo + zi * sAi;
    Bh += zo * sBo + zi * sBi;  Bl += zo * sBo + zi * sBi;
    C  += zo * sCo + zi * sCi;
    if (D) D += zo * sCo + zi * sCi;
    const int row0 = blockIdx.y * 128;
    const int col0 = blockIdx.x * 128;

    // cp.async geometry: 1024 16B-chunks per tile; 4 per thread per tile
    int rr[4], cc[4]; uint32_t swo[4];
    #pragma unroll
    for (int j = 0; j < 4; j++) {
        int idx = tid + j * 256;
        rr[j] = idx >> 3;
        cc[j] = idx & 7;
        swo[j] = (uint32_t)(rr[j] * 128 + ((cc[j] ^ (rr[j] & 7)) << 4));
    }
    const __nv_bfloat16* tp[4] = {Ah, Al, Bh, Bl};
    const int nk = K / KC;

    auto load_stage = [&](int s, int k0) {
        const uint32_t sb = dsm0 + s * STG_B;
        #pragma unroll
        for (int t = 0; t < 4; t++) {
            const __nv_bfloat16* g = tp[t];
            const long ld = (t < 2) ? lda : ldb;
            const int  rb = (t < 2) ? row0 : col0;
            const uint32_t tb = sb + t * TILE_B;
            #pragma unroll
            for (int j = 0; j < 4; j++)
                cpasync16(tb + swo[j], g + (long)(rb + rr[j]) * ld + k0 + cc[j] * 8);
        }
        cp_commit();
    };

    // ldmatrix lane geometry
    const int l7   = lane & 7;
    const int aRow = wm * 64 + l7 + ((lane >> 3) & 1) * 8;
    const int aSel = (lane >> 4) & 1;
    const int bRow = wn * 32 + l7;
    const int bSel = (lane >> 3) & 1;
    const uint32_t aRowOff = (uint32_t)aRow * 128;
    const uint32_t bRowOff = (uint32_t)bRow * 128;

    float acc[4][4][4];
    #pragma unroll
    for (int mt = 0; mt < 4; mt++)
        #pragma unroll
        for (int nt = 0; nt < 4; nt++)
            #pragma unroll
            for (int q = 0; q < 4; q++) acc[mt][nt][q] = 0.f;

    load_stage(0, 0);
    load_stage(1, KC);

    for (int i = 0; i < nk; ++i) {
        const int s = i % NSTAGE;
        if (i + 1 < nk) cp_wait<1>(); else cp_wait<0>();
        __syncthreads();
        if (i + 2 < nk) load_stage((i + 2) % NSTAGE, (i + 2) * KC);

        const uint32_t sb = dsm0 + s * STG_B;
        #pragma unroll
        for (int ks = 0; ks < 4; ++ks) {
            uint32_t ah[4][4], al[4][4], bh[4][2], bl[4][2];
            const uint32_t asw = (uint32_t)(((2 * ks + aSel) ^ l7) << 4);
            const uint32_t bsw = (uint32_t)(((2 * ks + bSel) ^ l7) << 4);
            #pragma unroll
            for (int mt = 0; mt < 4; mt++) {
                uint32_t ad = sb + aRowOff + mt * 2048 + asw;
                ldsm4(ah[mt], ad);
                ldsm4(al[mt], ad + TILE_B);
            }
            #pragma unroll
            for (int nt = 0; nt < 4; nt++) {
                uint32_t bd = sb + 2 * TILE_B + bRowOff + nt * 1024 + bsw;
                ldsm2(bh[nt], bd);
                ldsm2(bl[nt], bd + TILE_B);
            }
            #pragma unroll
            for (int mt = 0; mt < 4; mt++)
                #pragma unroll
                for (int nt = 0; nt < 4; nt++) {
                    mma16816(acc[mt][nt], ah[mt], bh[nt]);
                    mma16816(acc[mt][nt], ah[mt], bl[nt]);
                    mma16816(acc[mt][nt], al[mt], bh[nt]);
                }
        }
        __syncthreads();
    }

    // ---- epilogue
    const int cg = lane >> 2, tg = lane & 3;
    #pragma unroll
    for (int mt = 0; mt < 4; mt++) {
        #pragma unroll
        for (int nt = 0; nt < 4; nt++) {
            const int r = row0 + wm * 64 + mt * 16 + cg;
            const int c = col0 + wn * 32 + nt * 8 + tg * 2;
            float2 v0, v1;
            v0.x = acc[mt][nt][0] * alpha; v0.y = acc[mt][nt][1] * alpha;
            v1.x = acc[mt][nt][2] * alpha; v1.y = acc[mt][nt][3] * alpha;
            if (D) {
                float2 d0 = *(const float2*)(D + (long)r * ldc + c);
                float2 d1 = *(const float2*)(D + (long)(r + 8) * ldc + c);
                v0.x += d0.x; v0.y += d0.y; v1.x += d1.x; v1.y += d1.y;
            }
            *(float2*)(C + (long)r * ldc + c)       = v0;
            *(float2*)(C + (long)(r + 8) * ldc + c) = v1;
        }
    }
}

// ---------------------------------------------------------------------------
// fp32 -> bf16 hi/lo elementwise split
// ---------------------------------------------------------------------------
__global__ void split_kernel(const float* __restrict__ in,
                             __nv_bfloat16* __restrict__ hi,
                             __nv_bfloat16* __restrict__ lo, long n)
{
    long i = ((long)blockIdx.x * blockDim.x + threadIdx.x) * 4;
    if (i >= n) return;
    float4 v = *(const float4*)(in + i);
    __nv_bfloat16 h0 = __float2bfloat16(v.x), h1 = __float2bfloat16(v.y);
    __nv_bfloat16 h2 = __float2bfloat16(v.z), h3 = __float2bfloat16(v.w);
    __nv_bfloat162 ha, hb, la, lb;
    ha.x = h0; ha.y = h1; hb.x = h2; hb.y = h3;
    la.x = __float2bfloat16(v.x - __bfloat162float(h0));
    la.y = __float2bfloat16(v.y - __bfloat162float(h1));
    lb.x = __float2bfloat16(v.z - __bfloat162float(h2));
    lb.y = __float2bfloat16(v.w - __bfloat162float(h3));
    *(__nv_bfloat162*)(hi + i)     = ha;
    *(__nv_bfloat162*)(hi + i + 2) = hb;
    *(__nv_bfloat162*)(lo + i)     = la;
    *(__nv_bfloat162*)(lo + i + 2) = lb;
}

// ---------------------------------------------------------------------------
// fp32 [R,C] -> bf16 hi/lo transposed [C,R]  (batched via strides)
// ---------------------------------------------------------------------------
__global__ void tsplit_kernel(const float* __restrict__ in, long sIo, long sIi, int ldin,
                              __nv_bfloat16* __restrict__ hi, __nv_bfloat16* __restrict__ lo,
                              long sOo, long sOi, int ldo, int inner)
{
    __shared__ float tile[32][33];
    const int z = blockIdx.z, zo = z / inner, zi = z - zo * inner;
    in += zo * sIo + zi * sIi;
    hi += zo * sOo + zi * sOi;
    lo += zo * sOo + zi * sOi;
    const int r0 = blockIdx.y * 32, c0 = blockIdx.x * 32;
    const int tx = threadIdx.x, ty = threadIdx.y;
    #pragma unroll
    for (int i = 0; i < 4; i++)
        tile[ty + i * 8][tx] = in[(long)(r0 + ty + i * 8) * ldin + c0 + tx];
    __syncthreads();
    #pragma unroll
    for (int i = 0; i < 4; i++) {
        float v = tile[tx][ty + i * 8];
        __nv_bfloat16 h = __float2bfloat16(v);
        long o = (long)(c0 + ty + i * 8) * ldo + r0 + tx;
        hi[o] = h;
        lo[o] = __float2bfloat16(v - __bfloat162float(h));
    }
}

// ---------------------------------------------------------------------------
// build X, softmax, LN
// ---------------------------------------------------------------------------
__global__ void build_x_kernel(const float* __restrict__ ref,
                               const float* __restrict__ hd,
                               float* __restrict__ X)
{
    __shared__ float tile[32][33];
    const int b  = blockIdx.z;
    const int f0 = blockIdx.x * 32;
    const int t0 = blockIdx.y * 32;
    const int tx = threadIdx.x, ty = threadIdx.y;

#pragma unroll
    for (int i = 0; i < 4; i++) {
        int f  = f0 + ty + i * 8;
        int n_ = f >> 10;
        int s  = f & 1023;
        int hh = s >> 5;
        int ww = s & 31;
        const float* src = (ww < 16)
            ? ref + ((long)(((b * 8 + n_) * 32 + hh) * 16 + ww)) * 1024
            : hd  + ((long)(((b * 8 + n_) * 32 + hh) * 16 + (ww - 16))) * 1024;
        tile[ty + i * 8][tx] = src[t0 + tx];
    }
    __syncthreads();
#pragma unroll
    for (int i = 0; i < 4; i++) {
        int t = t0 + ty + i * 8;
        int f = f0 + tx;
        float freq = __expf((float)f * (-9.210340371976184f / 4096.0f));
        float ang  = (float)t * freq;
        float pe   = (f & 1) ? cosf(ang) : sinf(ang);
        X[(long)b * PLANE + (long)t * DEMB + f] = tile[tx][ty + i * 8] + 0.001f * pe;
    }
}

__global__ void softmax_kernel(float* __restrict__ S)
{
    __shared__ float red[8];
    const int tid  = threadIdx.x;
    const int lane = tid & 31, warp = tid >> 5;
    float4* row = (float4*)(S + (long)blockIdx.x * SEQ);
    float4 v = row[tid];

    float m = fmaxf(fmaxf(v.x, v.y), fmaxf(v.z, v.w));
#pragma unroll
    for (int o = 16; o; o >>= 1) m = fmaxf(m, __shfl_xor_sync(~0u, m, o));
    if (lane == 0) red[warp] = m;
    __syncthreads();
    float M = red[0];
#pragma unroll
    for (int i = 1; i < 8; i++) M = fmaxf(M, red[i]);

    v.x = __expf(v.x - M); v.y = __expf(v.y - M);
    v.z = __expf(v.z - M); v.w = __expf(v.w - M);
    float s = v.x + v.y + v.z + v.w;
#pragma unroll
    for (int o = 16; o; o >>= 1) s += __shfl_xor_sync(~0u, s, o);
    __syncthreads();
    if (lane == 0) red[warp] = s;
    __syncthreads();
    float T = 0.f;
#pragma unroll
    for (int i = 0; i < 8; i++) T += red[i];
    float inv = 1.0f / T;
    v.x *= inv; v.y *= inv; v.z *= inv; v.w *= inv;
    row[tid] = v;
}

__global__ void reduce_partial_kernel(const float* __restrict__ O,
                                      double* __restrict__ part)
{
    __shared__ double sh[256], sh2[256];
    const int b   = blockIdx.y;
    const int tid = threadIdx.x;
    const float* p = O + (long)b * PLANE;
    const int base = blockIdx.x * 256 + tid;
    double s = 0.0, s2 = 0.0;
#pragma unroll
    for (int i = 0; i < 32; i++) {
        float v = p[base + i * 262144];
        s  += v;
        s2 += (double)v * v;
    }
    sh[tid] = s; sh2[tid] = s2;
    __syncthreads();
    for (int o = 128; o; o >>= 1) {
        if (tid < o) { sh[tid] += sh[tid + o]; sh2[tid] += sh2[tid + o]; }
        __syncthreads();
    }
    if (tid == 0) {
        part[(b * 1024 + blockIdx.x) * 2 + 0] = sh[0];
        part[(b * 1024 + blockIdx.x) * 2 + 1] = sh2[0];
    }
}

__global__ void finalize_stats_kernel(const double* __restrict__ part)
{
    __shared__ double sh[256], sh2[256];
    const int b = blockIdx.x, tid = threadIdx.x;
    double s = 0.0, s2 = 0.0;
    for (int i = tid; i < 1024; i += 256) {
        s  += part[(b * 1024 + i) * 2 + 0];
        s2 += part[(b * 1024 + i) * 2 + 1];
    }
    sh[tid] = s; sh2[tid] = s2;
    __syncthreads();
    for (int o = 128; o; o >>= 1) {
        if (tid < o) { sh[tid] += sh[tid + o]; sh2[tid] += sh2[tid + o]; }
        __syncthreads();
    }
    if (tid == 0) {
        double n    = (double)PLANE;
        double mean = sh[0] / n;
        double var  = sh2[0] / n - mean * mean;
        g_mean[b] = mean;
        g_rstd[b] = rsqrt(var + 1e-6);
    }
}

__global__ void ln_out_kernel(const float* __restrict__ O,
                              const float* __restrict__ gamma,
                              const float* __restrict__ beta,
                              float* __restrict__ out)
{
    __shared__ float tile[32][33];
    const int bz = blockIdx.z;
    const int b  = bz >> 3;
    const int nf = (bz & 7) * 1024;
    const int c0 = blockIdx.x * 32;
    const int t0 = blockIdx.y * 32;
    const int tx = threadIdx.x, ty = threadIdx.y;
    const float mean = (float)g_mean[b];
    const float rstd = (float)g_rstd[b];

#pragma unroll
    for (int i = 0; i < 4; i++) {
        int t   = t0 + ty + i * 8;
        long fi = (long)t * DEMB + nf + c0 + tx;
        float v = O[(long)b * PLANE + fi];
        tile[ty + i * 8][tx] = (v - mean) * rstd * gamma[fi] + beta[fi];
    }
    __syncthreads();
#pragma unroll
    for (int i = 0; i < 4; i++) {
        int c = c0 + ty + i * 8;
        out[((long)bz * 1024 + c) * 1024 + t0 + tx] = tile[tx][ty + i * 8];
    }
}

// ---------------------------------------------------------------------------
// Launcher
// ---------------------------------------------------------------------------
extern "C" void kernel_launch(void* const* d_in, const int* in_sizes, int n_in,
                              void* d_out, int out_size)
{
    const float* ref_img = (const float*)d_in[0];
    const float* hdmap   = (const float*)d_in[1];
    const float* w_q     = (const float*)d_in[2];
    const float* w_k     = (const float*)d_in[3];
    const float* w_v     = (const float*)d_in[4];
    const float* w_o     = (const float*)d_in[5];
    const float* gamma   = (const float*)d_in[6];
    const float* beta    = (const float*)d_in[7];
    float* out = (float*)d_out;

    float *X, *Q, *Kf, *V, *S, *Z, *O;  double* part;
    __nv_bfloat16 *Xh, *Xl, *Wqth, *Wqtl, *Wkth, *Wktl, *Wvth, *Wvtl, *Woth, *Wotl;
    __nv_bfloat16 *Qh, *Ql, *Kh, *Kl, *Vth, *Vtl, *Ph, *Pl, *Zh, *Zl;
    cudaGetSymbolAddress((void**)&X, g_X);     cudaGetSymbolAddress((void**)&Q, g_Q);
    cudaGetSymbolAddress((void**)&Kf, g_K);    cudaGetSymbolAddress((void**)&V, g_V);
    cudaGetSymbolAddress((void**)&S, g_S);     cudaGetSymbolAddress((void**)&Z, g_Z);
    cudaGetSymbolAddress((void**)&O, g_O);     cudaGetSymbolAddress((void**)&part, g_part);
    cudaGetSymbolAddress((void**)&Xh, g_Xh);   cudaGetSymbolAddress((void**)&Xl, g_Xl);
    cudaGetSymbolAddress((void**)&Wqth, g_Wqth); cudaGetSymbolAddress((void**)&Wqtl, g_Wqtl);
    cudaGetSymbolAddress((void**)&Wkth, g_Wkth); cudaGetSymbolAddress((void**)&Wktl, g_Wktl);
    cudaGetSymbolAddress((void**)&Wvth, g_Wvth); cudaGetSymbolAddress((void**)&Wvtl, g_Wvtl);
    cudaGetSymbolAddress((void**)&Woth, g_Woth); cudaGetSymbolAddress((void**)&Wotl, g_Wotl);
    cudaGetSymbolAddress((void**)&Qh, g_Qh);   cudaGetSymbolAddress((void**)&Ql, g_Ql);
    cudaGetSymbolAddress((void**)&Kh, g_Kh);   cudaGetSymbolAddress((void**)&Kl, g_Kl);
    cudaGetSymbolAddress((void**)&Vth, g_Vth); cudaGetSymbolAddress((void**)&Vtl, g_Vtl);
    cudaGetSymbolAddress((void**)&Ph, g_Ph);   cudaGetSymbolAddress((void**)&Pl, g_Pl);
    cudaGetSymbolAddress((void**)&Zh, g_Zh);   cudaGetSymbolAddress((void**)&Zl, g_Zl);

    cudaFuncSetAttribute(mma_gemm, cudaFuncAttributeMaxDynamicSharedMemorySize, SMEM_DYN);

    const dim3 tb32x8(32, 8);

    // 1) build X (gather + transpose + PE), then split
    build_x_kernel<<<dim3(DEMB / 32, SEQ / 32, BATCH), tb32x8>>>(ref_img, hdmap, X);
    {
        long n = (long)BATCH * SEQ * DEMB;
        split_kernel<<<(unsigned)(n / 4 / 256), 256>>>(X, Xh, Xl, n);
    }

    // 2) weight transpose + split (w_q/k/v: [8192,2048] -> [2048,8192])
    tsplit_kernel<<<dim3(QKVDIM / 32, DEMB / 32, 1), tb32x8>>>(w_q, 0, 0, QKVDIM, Wqth, Wqtl, 0, 0, DEMB, 1);
    tsplit_kernel<<<dim3(QKVDIM / 32, DEMB / 32, 1), tb32x8>>>(w_k, 0, 0, QKVDIM, Wkth, Wktl, 0, 0, DEMB, 1);
    tsplit_kernel<<<dim3(QKVDIM / 32, DEMB / 32, 1), tb32x8>>>(w_v, 0, 0, QKVDIM, Wvth, Wvtl, 0, 0, DEMB, 1);
    tsplit_kernel<<<dim3(DEMB / 32, QKVDIM / 32, 1), tb32x8>>>(w_o, 0, 0, DEMB, Woth, Wotl, 0, 0, QKVDIM, 1);

    // 3) Q/K/V projections on HMMA
    const dim3 gqkv(QKVDIM / 128, TOK_TOTAL / 128, 1);
    mma_gemm<<<gqkv, 256, SMEM_DYN>>>(Xh, Xl, DEMB, 0, 0, Wqth, Wqtl, DEMB, 0, 0,
                                      Q, QKVDIM, 0, 0, nullptr, DEMB, 1, 1.0f);
    mma_gemm<<<gqkv, 256, SMEM_DYN>>>(Xh, Xl, DEMB, 0, 0, Wkth, Wktl, DEMB, 0, 0,
                                      Kf, QKVDIM, 0, 0, nullptr, DEMB, 1, 1.0f);
    mma_gemm<<<gqkv, 256, SMEM_DYN>>>(Xh, Xl, DEMB, 0, 0, Wvth, Wvtl, DEMB, 0, 0,
                                      V, QKVDIM, 0, 0, nullptr, DEMB, 1, 1.0f);

    // 4) split Q/K; transpose+split V per head -> Vt[b,h,d,t]
    {
        long n = (long)BATCH * SEQ * QKVDIM;
        split_kernel<<<(unsigned)(n / 4 / 256), 256>>>(Q, Qh, Ql, n);
        split_kernel<<<(unsigned)(n / 4 / 256), 256>>>(Kf, Kh, Kl, n);
    }
    tsplit_kernel<<<dim3(DKV / 32, SEQ / 32, BATCH * NHEAD), tb32x8>>>(
        V, (long)SEQ * QKVDIM, DKV, QKVDIM,
        Vth, Vtl, (long)NHEAD * DKV * SEQ, (long)DKV * SEQ, SEQ, NHEAD);

    // 5) scores S = (1/16) Q K^T per (b,h)
    const long sQKo = (long)SEQ * QKVDIM;
    const long sSo  = (long)NHEAD * SEQ * SEQ;
    mma_gemm<<<dim3(SEQ / 128, SEQ / 128, BATCH * NHEAD), 256, SMEM_DYN>>>(
        Qh, Ql, QKVDIM, sQKo, DKV,
        Kh, Kl, QKVDIM, sQKo, DKV,
        S, SEQ, sSo, (long)SEQ * SEQ, nullptr,
        DKV, NHEAD, 0.0625f);

    // 6) softmax + split P
    softmax_kernel<<<BATCH * NHEAD * SEQ, 256>>>(S);
    {
        long n = (long)BATCH * NHEAD * SEQ * SEQ;
        split_kernel<<<(unsigned)(n / 4 / 256), 256>>>(S, Ph, Pl, n);
    }

    // 7) Z = P @ V per (b,h)   (B operand = Vt[d,t])
    mma_gemm<<<dim3(DKV / 128, SEQ / 128, BATCH * NHEAD), 256, SMEM_DYN>>>(
        Ph, Pl, SEQ, sSo, (long)SEQ * SEQ,
        Vth, Vtl, SEQ, (long)NHEAD * DKV * SEQ, (long)DKV * SEQ,
        Z, QKVDIM, sQKo, DKV, nullptr,
        SEQ, NHEAD, 1.0f);

    // 8) split Z, then O = Z @ w_o + X
    {
        long n = (long)BATCH * SEQ * QKVDIM;
        split_kernel<<<(unsigned)(n / 4 / 256), 256>>>(Z, Zh, Zl, n);
    }
    mma_gemm<<<dim3(DEMB / 128, TOK_TOTAL / 128, 1), 256, SMEM_DYN>>>(
        Zh, Zl, QKVDIM, 0, 0, Woth, Wotl, QKVDIM, 0, 0,
        O, DEMB, 0, 0, X,
        QKVDIM, 1, 1.0f);

    // 9) LayerNorm stats + normalize/transpose out
    reduce_partial_kernel<<<dim3(1024, BATCH), 256>>>(O, part);
    finalize_stats_kernel<<<BATCH, 256>>>(part);
    ln_out_kernel<<<dim3(32, 32, BATCH * NHEAD), tb32x8>>>(O, gamma, beta, out);
}

// round 7
// speedup vs baseline: 3.0350x; 1.0106x over previous
#include <cuda_runtime.h>
#include <cuda_bf16.h>
#include <cstdint>
#include <math.h>

// ---------------------------------------------------------------------------
// Problem constants
// ---------------------------------------------------------------------------
#define BATCH      4
#define SEQ        1024
#define DEMB       8192
#define NHEAD      8
#define DKV        256
#define QKVDIM     (NHEAD * DKV)          // 2048
#define TOK_TOTAL  (BATCH * SEQ)          // 4096
#define PLANE      ((long)SEQ * DEMB)

// ---------------------------------------------------------------------------
// Scratch (static device allocations — no cudaMalloc allowed)
// ---------------------------------------------------------------------------
__device__ __align__(256) float  g_X[(long)BATCH * SEQ * DEMB];
__device__ __align__(256) float  g_V[(long)BATCH * SEQ * QKVDIM];
__device__ __align__(256) float  g_S[(long)BATCH * NHEAD * SEQ * SEQ];
__device__ __align__(256) float  g_O[(long)BATCH * SEQ * DEMB];
__device__ double g_part[BATCH * 1024 * 2];
__device__ double g_mean[BATCH];
__device__ double g_rstd[BATCH];

// bf16 hi/lo split operands
__device__ __align__(256) __nv_bfloat16 g_Xh[(long)BATCH * SEQ * DEMB];
__device__ __align__(256) __nv_bfloat16 g_Xl[(long)BATCH * SEQ * DEMB];
__device__ __align__(256) __nv_bfloat16 g_Wqth[(long)QKVDIM * DEMB];
__device__ __align__(256) __nv_bfloat16 g_Wqtl[(long)QKVDIM * DEMB];
__device__ __align__(256) __nv_bfloat16 g_Wkth[(long)QKVDIM * DEMB];
__device__ __align__(256) __nv_bfloat16 g_Wktl[(long)QKVDIM * DEMB];
__device__ __align__(256) __nv_bfloat16 g_Wvth[(long)QKVDIM * DEMB];
__device__ __align__(256) __nv_bfloat16 g_Wvtl[(long)QKVDIM * DEMB];
__device__ __align__(256) __nv_bfloat16 g_Woth[(long)DEMB * QKVDIM];
__device__ __align__(256) __nv_bfloat16 g_Wotl[(long)DEMB * QKVDIM];
__device__ __align__(256) __nv_bfloat16 g_Qh[(long)BATCH * SEQ * QKVDIM];
__device__ __align__(256) __nv_bfloat16 g_Ql[(long)BATCH * SEQ * QKVDIM];
__device__ __align__(256) __nv_bfloat16 g_Kh[(long)BATCH * SEQ * QKVDIM];
__device__ __align__(256) __nv_bfloat16 g_Kl[(long)BATCH * SEQ * QKVDIM];
__device__ __align__(256) __nv_bfloat16 g_Vth[(long)BATCH * NHEAD * DKV * SEQ];
__device__ __align__(256) __nv_bfloat16 g_Vtl[(long)BATCH * NHEAD * DKV * SEQ];
__device__ __align__(256) __nv_bfloat16 g_Ph[(long)BATCH * NHEAD * SEQ * SEQ];
__device__ __align__(256) __nv_bfloat16 g_Pl[(long)BATCH * NHEAD * SEQ * SEQ];
__device__ __align__(256) __nv_bfloat16 g_Zh[(long)BATCH * SEQ * QKVDIM];
__device__ __align__(256) __nv_bfloat16 g_Zl[(long)BATCH * SEQ * QKVDIM];

// ---------------------------------------------------------------------------
// PTX helpers (sm_80-compatible: cp.async, ldmatrix, mma.sync)
// ---------------------------------------------------------------------------
__device__ __forceinline__ uint32_t smem_u32(const void* p) {
    uint32_t a;
    asm("{ .reg .u64 t; cvta.to.shared.u64 t, %1; cvt.u32.u64 %0, t; }"
        : "=r"(a) : "l"(p));
    return a;
}
__device__ __forceinline__ void cpasync16(uint32_t dst, const void* src) {
    asm volatile("cp.async.cg.shared.global [%0], [%1], 16;" :: "r"(dst), "l"(src));
}
__device__ __forceinline__ void cp_commit() {
    asm volatile("cp.async.commit_group;" ::: "memory");
}
template <int N> __device__ __forceinline__ void cp_wait() {
    asm volatile("cp.async.wait_group %0;" :: "n"(N) : "memory");
}
__device__ __forceinline__ void ldsm4(uint32_t* r, uint32_t addr) {
    asm volatile("ldmatrix.sync.aligned.m8n8.x4.shared.b16 {%0,%1,%2,%3}, [%4];"
                 : "=r"(r[0]), "=r"(r[1]), "=r"(r[2]), "=r"(r[3]) : "r"(addr));
}
__device__ __forceinline__ void ldsm2(uint32_t* r, uint32_t addr) {
    asm volatile("ldmatrix.sync.aligned.m8n8.x2.shared.b16 {%0,%1}, [%2];"
                 : "=r"(r[0]), "=r"(r[1]) : "r"(addr));
}
__device__ __forceinline__ void mma16816(float* c, const uint32_t* a, const uint32_t* b) {
    asm volatile(
        "mma.sync.aligned.m16n8k16.row.col.f32.bf16.bf16.f32 "
        "{%0,%1,%2,%3}, {%4,%5,%6,%7}, {%8,%9}, {%0,%1,%2,%3};"
        : "+f"(c[0]), "+f"(c[1]), "+f"(c[2]), "+f"(c[3])
        : "r"(a[0]), "r"(a[1]), "r"(a[2]), "r"(a[3]), "r"(b[0]), "r"(b[1]));
}
__device__ __forceinline__ __nv_bfloat162 split_hi2(float x, float y) {
    __nv_bfloat162 h;
    h.x = __float2bfloat16(x); h.y = __float2bfloat16(y);
    return h;
}
__device__ __forceinline__ __nv_bfloat162 split_lo2(float x, float y, __nv_bfloat162 h) {
    __nv_bfloat162 l;
    l.x = __float2bfloat16(x - __bfloat162float(h.x));
    l.y = __float2bfloat16(y - __bfloat162float(h.y));
    return l;
}

// ---------------------------------------------------------------------------
// Split-precision bf16 GEMM on mma.sync (HMMA).
// acc = alpha * (Ah*Bh^T + Ah*Bl^T + Al*Bh^T) (+ D), fp32 accum in regs.
// Outputs: optional fp32 Cf, optional bf16 hi/lo pair (Ch, Cl). Same ldc.
// A*: [M,K] bf16 row-major (lda). B*: [N,K] bf16 row-major (ldb).
// Block 128x128, K-chunk 64, 3-stage cp.async pipeline, XOR-swizzled smem.
// Grouped rasterization (GROUP=8 M-tiles) for L2 reuse.
// Batch z: offset = (z/inner)*so + (z%inner)*si per operand.
// ---------------------------------------------------------------------------
#define KC      64
#define TILE_B  16384                     // 128 rows x 128 bytes
#define STG_B   (4 * TILE_B)              // Ah, Al, Bh, Bl per stage
#define NSTAGE  3
#define SMEM_DYN (NSTAGE * STG_B)         // 196608

__global__ __launch_bounds__(256, 1)
void mma_gemm(const __nv_bfloat16* __restrict__ Ah, const __nv_bfloat16* __restrict__ Al,
              int lda, long sAo, long sAi,
              const __nv_bfloat16* __restrict__ Bh, const __nv_bfloat16* __restrict__ Bl,
              int ldb, long sBo, long sBi,
              float* __restrict__ Cf,
              __nv_bfloat16* __restrict__ Ch, __nv_bfloat16* __restrict__ Cl,
              int ldc, long sCo, long sCi,
              const float* __restrict__ D,
              int K, int inner, float alpha)
{
    extern __shared__ char dsm_raw[];
    const uint32_t dsm0 = smem_u32(dsm_raw);

    const int tid  = threadIdx.x;
    const int lane = tid & 31;
    const int wid  = tid >> 5;
    const int wm   = wid & 1;             // warp row (2)
    const int wn   = wid >> 1;            // warp col (4)

    const int z  = blockIdx.z;
    const int zo = z / inner, zi = z - zo * inner;
    Ah += zo * sAo + zi * sAi;  Al += zo * sAo + zi * sAi;
    Bh += zo * sBo + zi * sBi;  Bl += zo * sBo + zi * sBi;
    const long coff = zo * sCo + zi * sCi;
    if (Cf) Cf += coff;
    if (Ch) { Ch += coff; Cl += coff; }
    if (D)  D  += coff;

    // grouped rasterization: GROUP M-tiles per stripe, sweep N within stripe
    int pid_m, pid_n;
    {
        const int ntm = gridDim.y, ntn = gridDim.x;
        const int lin = blockIdx.y * ntn + blockIdx.x;
        const int G = 8;
        const int width = G * ntn;
        const int grp = lin / width;
        const int rem = lin - grp * width;
        const int m0  = grp * G;
        const int gsz = (ntm - m0 < G) ? (ntm - m0) : G;
        pid_m = m0 + rem % gsz;
        pid_n = rem / gsz;
    }
    const int row0 = pid_m * 128;
    const int col0 = pid_n * 128;

    // cp.async geometry: 1024 16B-chunks per tile; 4 per thread per tile
    int rr[4], cc[4]; uint32_t swo[4];
    #pragma unroll
    for (int j = 0; j < 4; j++) {
        int idx = tid + j * 256;
        rr[j] = idx >> 3;
        cc[j] = idx & 7;
        swo[j] = (uint32_t)(rr[j] * 128 + ((cc[j] ^ (rr[j] & 7)) << 4));
    }
    const __nv_bfloat16* tp[4] = {Ah, Al, Bh, Bl};
    const int nk = K / KC;

    auto load_stage = [&](int s, int k0) {
        const uint32_t sb = dsm0 + s * STG_B;
        #pragma unroll
        for (int t = 0; t < 4; t++) {
            const __nv_bfloat16* g = tp[t];
            const long ld = (t < 2) ? lda : ldb;
            const int  rb = (t < 2) ? row0 : col0;
            const uint32_t tb = sb + t * TILE_B;
            #pragma unroll
            for (int j = 0; j < 4; j++)
                cpasync16(tb + swo[j], g + (long)(rb + rr[j]) * ld + k0 + cc[j] * 8);
        }
        cp_commit();
    };

    // ldmatrix lane geometry
    const int l7   = lane & 7;
    const int aRow = wm * 64 + l7 + ((lane >> 3) & 1) * 8;
    const int aSel = (lane >> 4) & 1;
    const int bRow = wn * 32 + l7;
    const int bSel = (lane >> 3) & 1;
    const uint32_t aRowOff = (uint32_t)aRow * 128;
    const uint32_t bRowOff = (uint32_t)bRow * 128;

    float acc[4][4][4];
    #pragma unroll
    for (int mt = 0; mt < 4; mt++)
        #pragma unroll
        for (int nt = 0; nt < 4; nt++)
            #pragma unroll
            for (int q = 0; q < 4; q++) acc[mt][nt][q] = 0.f;

    load_stage(0, 0);
    load_stage(1, KC);

    for (int i = 0; i < nk; ++i) {
        const int s = i % NSTAGE;
        if (i + 1 < nk) cp_wait<1>(); else cp_wait<0>();
        __syncthreads();
        if (i + 2 < nk) load_stage((i + 2) % NSTAGE, (i + 2) * KC);

        const uint32_t sb = dsm0 + s * STG_B;
        #pragma unroll
        for (int ks = 0; ks < 4; ++ks) {
            uint32_t ah[4][4], al[4][4], bh[4][2], bl[4][2];
            const uint32_t asw = (uint32_t)(((2 * ks + aSel) ^ l7) << 4);
            const uint32_t bsw = (uint32_t)(((2 * ks + bSel) ^ l7) << 4);
            #pragma unroll
            for (int mt = 0; mt < 4; mt++) {
                uint32_t ad = sb + aRowOff + mt * 2048 + asw;
                ldsm4(ah[mt], ad);
                ldsm4(al[mt], ad + TILE_B);
            }
            #pragma unroll
            for (int nt = 0; nt < 4; nt++) {
                uint32_t bd = sb + 2 * TILE_B + bRowOff + nt * 1024 + bsw;
                ldsm2(bh[nt], bd);
                ldsm2(bl[nt], bd + TILE_B);
            }
            #pragma unroll
            for (int mt = 0; mt < 4; mt++)
                #pragma unroll
                for (int nt = 0; nt < 4; nt++) {
                    mma16816(acc[mt][nt], ah[mt], bh[nt]);
                    mma16816(acc[mt][nt], ah[mt], bl[nt]);
                    mma16816(acc[mt][nt], al[mt], bh[nt]);
                }
        }
        __syncthreads();
    }

    // ---- epilogue: fp32 and/or bf16 hi/lo split outputs
    const int cg = lane >> 2, tg = lane & 3;
    #pragma unroll
    for (int mt = 0; mt < 4; mt++) {
        #pragma unroll
        for (int nt = 0; nt < 4; nt++) {
            const int r = row0 + wm * 64 + mt * 16 + cg;
            const int c = col0 + wn * 32 + nt * 8 + tg * 2;
            const long o0 = (long)r * ldc + c;
            const long o1 = (long)(r + 8) * ldc + c;
            float2 v0, v1;
            v0.x = acc[mt][nt][0] * alpha; v0.y = acc[mt][nt][1] * alpha;
            v1.x = acc[mt][nt][2] * alpha; v1.y = acc[mt][nt][3] * alpha;
            if (D) {
                float2 d0 = *(const float2*)(D + o0);
                float2 d1 = *(const float2*)(D + o1);
                v0.x += d0.x; v0.y += d0.y; v1.x += d1.x; v1.y += d1.y;
            }
            if (Cf) {
                *(float2*)(Cf + o0) = v0;
                *(float2*)(Cf + o1) = v1;
            }
            if (Ch) {
                __nv_bfloat162 h0 = split_hi2(v0.x, v0.y);
                __nv_bfloat162 h1 = split_hi2(v1.x, v1.y);
                *(__nv_bfloat162*)(Ch + o0) = h0;
                *(__nv_bfloat162*)(Ch + o1) = h1;
                *(__nv_bfloat162*)(Cl + o0) = split_lo2(v0.x, v0.y, h0);
                *(__nv_bfloat162*)(Cl + o1) = split_lo2(v1.x, v1.y, h1);
            }
        }
    }
}

// ---------------------------------------------------------------------------
// fp32 [R,C] -> bf16 hi/lo transposed [C,R]  (batched via strides)
// ---------------------------------------------------------------------------
__global__ void tsplit_kernel(const float* __restrict__ in, long sIo, long sIi, int ldin,
                              __nv_bfloat16* __restrict__ hi, __nv_bfloat16* __restrict__ lo,
                              long sOo, long sOi, int ldo, int inner)
{
    __shared__ float tile[32][33];
    const int z = blockIdx.z, zo = z / inner, zi = z - zo * inner;
    in += zo * sIo + zi * sIi;
    hi += zo * sOo + zi * sOi;
    lo += zo * sOo + zi * sOi;
    const int r0 = blockIdx.y * 32, c0 = blockIdx.x * 32;
    const int tx = threadIdx.x, ty = threadIdx.y;
    #pragma unroll
    for (int i = 0; i < 4; i++)
        tile[ty + i * 8][tx] = in[(long)(r0 + ty + i * 8) * ldin + c0 + tx];
    __syncthreads();
    #pragma unroll
    for (int i = 0; i < 4; i++) {
        float v = tile[tx][ty + i * 8];
        __nv_bfloat16 h = __float2bfloat16(v);
        long o = (long)(c0 + ty + i * 8) * ldo + r0 + tx;
        hi[o] = h;
        lo[o] = __float2bfloat16(v - __bfloat162float(h));
    }
}

// ---------------------------------------------------------------------------
// build X (gather + transpose + PE) writing fp32 AND bf16 hi/lo
// ---------------------------------------------------------------------------
__global__ void build_x_kernel(const float* __restrict__ ref,
                               const float* __restrict__ hd,
                               float* __restrict__ X,
                               __nv_bfloat16* __restrict__ Xh,
                               __nv_bfloat16* __restrict__ Xl)
{
    __shared__ float tile[32][33];
    const int b  = blockIdx.z;
    const int f0 = blockIdx.x * 32;
    const int t0 = blockIdx.y * 32;
    const int tx = threadIdx.x, ty = threadIdx.y;

#pragma unroll
    for (int i = 0; i < 4; i++) {
        int f  = f0 + ty + i * 8;
        int n_ = f >> 10;
        int s  = f & 1023;
        int hh = s >> 5;
        int ww = s & 31;
        const float* src = (ww < 16)
            ? ref + ((long)(((b * 8 + n_) * 32 + hh) * 16 + ww)) * 1024
            : hd  + ((long)(((b * 8 + n_) * 32 + hh) * 16 + (ww - 16))) * 1024;
        tile[ty + i * 8][tx] = src[t0 + tx];
    }
    __syncthreads();
#pragma unroll
    for (int i = 0; i < 4; i++) {
        int t = t0 + ty + i * 8;
        int f = f0 + tx;
        float freq = __expf((float)f * (-9.210340371976184f / 4096.0f));
        float ang  = (float)t * freq;
        float pe   = (f & 1) ? cosf(ang) : sinf(ang);
        float v    = tile[tx][ty + i * 8] + 0.001f * pe;
        long  o    = (long)b * PLANE + (long)t * DEMB + f;
        X[o] = v;
        __nv_bfloat16 h = __float2bfloat16(v);
        Xh[o] = h;
        Xl[o] = __float2bfloat16(v - __bfloat162float(h));
    }
}

// ---------------------------------------------------------------------------
// Softmax over rows of S, writing bf16 hi/lo P directly.
// ---------------------------------------------------------------------------
__global__ void softmax_kernel(const float* __restrict__ S,
                               __nv_bfloat16* __restrict__ Ph,
                               __nv_bfloat16* __restrict__ Pl)
{
    __shared__ float red[8];
    const int tid  = threadIdx.x;
    const int lane = tid & 31, warp = tid >> 5;
    const float4* row = (const float4*)(S + (long)blockIdx.x * SEQ);
    float4 v = row[tid];

    float m = fmaxf(fmaxf(v.x, v.y), fmaxf(v.z, v.w));
#pragma unroll
    for (int o = 16; o; o >>= 1) m = fmaxf(m, __shfl_xor_sync(~0u, m, o));
    if (lane == 0) red[warp] = m;
    __syncthreads();
    float M = red[0];
#pragma unroll
    for (int i = 1; i < 8; i++) M = fmaxf(M, red[i]);

    v.x = __expf(v.x - M); v.y = __expf(v.y - M);
    v.z = __expf(v.z - M); v.w = __expf(v.w - M);
    float s = v.x + v.y + v.z + v.w;
#pragma unroll
    for (int o = 16; o; o >>= 1) s += __shfl_xor_sync(~0u, s, o);
    __syncthreads();
    if (lane == 0) red[warp] = s;
    __syncthreads();
    float T = 0.f;
#pragma unroll
    for (int i = 0; i < 8; i++) T += red[i];
    float inv = 1.0f / T;
    v.x *= inv; v.y *= inv; v.z *= inv; v.w *= inv;

    const long o = (long)blockIdx.x * SEQ + tid * 4;
    __nv_bfloat162 h0 = split_hi2(v.x, v.y);
    __nv_bfloat162 h1 = split_hi2(v.z, v.w);
    *(__nv_bfloat162*)(Ph + o)     = h0;
    *(__nv_bfloat162*)(Ph + o + 2) = h1;
    *(__nv_bfloat162*)(Pl + o)     = split_lo2(v.x, v.y, h0);
    *(__nv_bfloat162*)(Pl + o + 2) = split_lo2(v.z, v.w, h1);
}

// ---------------------------------------------------------------------------
// LayerNorm statistics (deterministic two-stage, fp64)
// ---------------------------------------------------------------------------
__global__ void reduce_partial_kernel(const float* __restrict__ O,
                                      double* __restrict__ part)
{
    __shared__ double sh[256], sh2[256];
    const int b   = blockIdx.y;
    const int tid = threadIdx.x;
    const float* p = O + (long)b * PLANE;
    const int base = blockIdx.x * 256 + tid;
    double s = 0.0, s2 = 0.0;
#pragma unroll
    for (int i = 0; i < 32; i++) {
        float v = p[base + i * 262144];
        s  += v;
        s2 += (double)v * v;
    }
    sh[tid] = s; sh2[tid] = s2;
    __syncthreads();
    for (int o = 128; o; o >>= 1) {
        if (tid < o) { sh[tid] += sh[tid + o]; sh2[tid] += sh2[tid + o]; }
        __syncthreads();
    }
    if (tid == 0) {
        part[(b * 1024 + blockIdx.x) * 2 + 0] = sh[0];
        part[(b * 1024 + blockIdx.x) * 2 + 1] = sh2[0];
    }
}

__global__ void finalize_stats_kernel(const double* __restrict__ part)
{
    __shared__ double sh[256], sh2[256];
    const int b = blockIdx.x, tid = threadIdx.x;
    double s = 0.0, s2 = 0.0;
    for (int i = tid; i < 1024; i += 256) {
        s  += part[(b * 1024 + i) * 2 + 0];
        s2 += part[(b * 1024 + i) * 2 + 1];
    }
    sh[tid] = s; sh2[tid] = s2;
    __syncthreads();
    for (int o = 128; o; o >>= 1) {
        if (tid < o) { sh[tid] += sh[tid + o]; sh2[tid] += sh2[tid + o]; }
        __syncthreads();
    }
    if (tid == 0) {
        double n    = (double)PLANE;
        double mean = sh[0] / n;
        double var  = sh2[0] / n - mean * mean;
        g_mean[b] = mean;
        g_rstd[b] = rsqrt(var + 1e-6);
    }
}

__global__ void ln_out_kernel(const float* __restrict__ O,
                              const float* __restrict__ gamma,
                              const float* __restrict__ beta,
                              float* __restrict__ out)
{
    __shared__ float tile[32][33];
    const int bz = blockIdx.z;
    const int b  = bz >> 3;
    const int nf = (bz & 7) * 1024;
    const int c0 = blockIdx.x * 32;
    const int t0 = blockIdx.y * 32;
    const int tx = threadIdx.x, ty = threadIdx.y;
    const float mean = (float)g_mean[b];
    const float rstd = (float)g_rstd[b];

#pragma unroll
    for (int i = 0; i < 4; i++) {
        int t   = t0 + ty + i * 8;
        long fi = (long)t * DEMB + nf + c0 + tx;
        float v = O[(long)b * PLANE + fi];
        tile[ty + i * 8][tx] = (v - mean) * rstd * gamma[fi] + beta[fi];
    }
    __syncthreads();
#pragma unroll
    for (int i = 0; i < 4; i++) {
        int c = c0 + ty + i * 8;
        out[((long)bz * 1024 + c) * 1024 + t0 + tx] = tile[tx][ty + i * 8];
    }
}

// ---------------------------------------------------------------------------
// Launcher
// ---------------------------------------------------------------------------
extern "C" void kernel_launch(void* const* d_in, const int* in_sizes, int n_in,
                              void* d_out, int out_size)
{
    const float* ref_img = (const float*)d_in[0];
    const float* hdmap   = (const float*)d_in[1];
    const float* w_q     = (const float*)d_in[2];
    const float* w_k     = (const float*)d_in[3];
    const float* w_v     = (const float*)d_in[4];
    const float* w_o     = (const float*)d_in[5];
    const float* gamma   = (const float*)d_in[6];
    const float* beta    = (const float*)d_in[7];
    float* out = (float*)d_out;

    float *X, *V, *S, *O;  double* part;
    __nv_bfloat16 *Xh, *Xl, *Wqth, *Wqtl, *Wkth, *Wktl, *Wvth, *Wvtl, *Woth, *Wotl;
    __nv_bfloat16 *Qh, *Ql, *Kh, *Kl, *Vth, *Vtl, *Ph, *Pl, *Zh, *Zl;
    cudaGetSymbolAddress((void**)&X, g_X);     cudaGetSymbolAddress((void**)&V, g_V);
    cudaGetSymbolAddress((void**)&S, g_S);     cudaGetSymbolAddress((void**)&O, g_O);
    cudaGetSymbolAddress((void**)&part, g_part);
    cudaGetSymbolAddress((void**)&Xh, g_Xh);   cudaGetSymbolAddress((void**)&Xl, g_Xl);
    cudaGetSymbolAddress((void**)&Wqth, g_Wqth); cudaGetSymbolAddress((void**)&Wqtl, g_Wqtl);
    cudaGetSymbolAddress((void**)&Wkth, g_Wkth); cudaGetSymbolAddress((void**)&Wktl, g_Wktl);
    cudaGetSymbolAddress((void**)&Wvth, g_Wvth); cudaGetSymbolAddress((void**)&Wvtl, g_Wvtl);
    cudaGetSymbolAddress((void**)&Woth, g_Woth); cudaGetSymbolAddress((void**)&Wotl, g_Wotl);
    cudaGetSymbolAddress((void**)&Qh, g_Qh);   cudaGetSymbolAddress((void**)&Ql, g_Ql);
    cudaGetSymbolAddress((void**)&Kh, g_Kh);   cudaGetSymbolAddress((void**)&Kl, g_Kl);
    cudaGetSymbolAddress((void**)&Vth, g_Vth); cudaGetSymbolAddress((void**)&Vtl, g_Vtl);
    cudaGetSymbolAddress((void**)&Ph, g_Ph);   cudaGetSymbolAddress((void**)&Pl, g_Pl);
    cudaGetSymbolAddress((void**)&Zh, g_Zh);   cudaGetSymbolAddress((void**)&Zl, g_Zl);

    cudaFuncSetAttribute(mma_gemm, cudaFuncAttributeMaxDynamicSharedMemorySize, SMEM_DYN);

    const dim3 tb32x8(32, 8);

    // 1) build X (gather + transpose + PE) with fused hi/lo split
    build_x_kernel<<<dim3(DEMB / 32, SEQ / 32, BATCH), tb32x8>>>(ref_img, hdmap, X, Xh, Xl);

    // 2) weight transpose + split
    tsplit_kernel<<<dim3(QKVDIM / 32, DEMB / 32, 1), tb32x8>>>(w_q, 0, 0, QKVDIM, Wqth, Wqtl, 0, 0, DEMB, 1);
    tsplit_kernel<<<dim3(QKVDIM / 32, DEMB / 32, 1), tb32x8>>>(w_k, 0, 0, QKVDIM, Wkth, Wktl, 0, 0, DEMB, 1);
    tsplit_kernel<<<dim3(QKVDIM / 32, DEMB / 32, 1), tb32x8>>>(w_v, 0, 0, QKVDIM, Wvth, Wvtl, 0, 0, DEMB, 1);
    tsplit_kernel<<<dim3(DEMB / 32, QKVDIM / 32, 1), tb32x8>>>(w_o, 0, 0, DEMB, Woth, Wotl, 0, 0, QKVDIM, 1);

    // 3) Q/K/V projections; Q,K write split directly, V stays fp32
    const dim3 gqkv(QKVDIM / 128, TOK_TOTAL / 128, 1);
    mma_gemm<<<gqkv, 256, SMEM_DYN>>>(Xh, Xl, DEMB, 0, 0, Wqth, Wqtl, DEMB, 0, 0,
                                      nullptr, Qh, Ql, QKVDIM, 0, 0, nullptr, DEMB, 1, 1.0f);
    mma_gemm<<<gqkv, 256, SMEM_DYN>>>(Xh, Xl, DEMB, 0, 0, Wkth, Wktl, DEMB, 0, 0,
                                      nullptr, Kh, Kl, QKVDIM, 0, 0, nullptr, DEMB, 1, 1.0f);
    mma_gemm<<<gqkv, 256, SMEM_DYN>>>(Xh, Xl, DEMB, 0, 0, Wvth, Wvtl, DEMB, 0, 0,
                                      V, nullptr, nullptr, QKVDIM, 0, 0, nullptr, DEMB, 1, 1.0f);

    // 4) transpose+split V per head -> Vt[b,h,d,t]
    tsplit_kernel<<<dim3(DKV / 32, SEQ / 32, BATCH * NHEAD), tb32x8>>>(
        V, (long)SEQ * QKVDIM, DKV, QKVDIM,
        Vth, Vtl, (long)NHEAD * DKV * SEQ, (long)DKV * SEQ, SEQ, NHEAD);

    // 5) scores S = (1/16) Q K^T per (b,h)
    const long sQKo = (long)SEQ * QKVDIM;
    const long sSo  = (long)NHEAD * SEQ * SEQ;
    mma_gemm<<<dim3(SEQ / 128, SEQ / 128, BATCH * NHEAD), 256, SMEM_DYN>>>(
        Qh, Ql, QKVDIM, sQKo, DKV,
        Kh, Kl, QKVDIM, sQKo, DKV,
        S, nullptr, nullptr, SEQ, sSo, (long)SEQ * SEQ, nullptr,
        DKV, NHEAD, 0.0625f);

    // 6) softmax with fused P split
    softmax_kernel<<<BATCH * NHEAD * SEQ, 256>>>(S, Ph, Pl);

    // 7) Z = P @ V per (b,h), writes Zh/Zl directly
    mma_gemm<<<dim3(DKV / 128, SEQ / 128, BATCH * NHEAD), 256, SMEM_DYN>>>(
        Ph, Pl, SEQ, sSo, (long)SEQ * SEQ,
        Vth, Vtl, SEQ, (long)NHEAD * DKV * SEQ, (long)DKV * SEQ,
        nullptr, Zh, Zl, QKVDIM, sQKo, DKV, nullptr,
        SEQ, NHEAD, 1.0f);

    // 8) O = Z @ w_o + X (residual)
    mma_gemm<<<dim3(DEMB / 128, TOK_TOTAL / 128, 1), 256, SMEM_DYN>>>(
        Zh, Zl, QKVDIM, 0, 0, Woth, Wotl, QKVDIM, 0, 0,
        O, nullptr, nullptr, DEMB, 0, 0, X,
        QKVDIM, 1, 1.0f);

    // 9) LayerNorm stats + normalize/transpose out
    reduce_partial_kernel<<<dim3(1024, BATCH), 256>>>(O, part);
    finalize_stats_kernel<<<BATCH, 256>>>(part);
    ln_out_kernel<<<dim3(32, 32, BATCH * NHEAD), tb32x8>>>(O, gamma, beta, out);
}